// round 6
// baseline (speedup 1.0000x reference)
#include <cuda_runtime.h>

#define NN   200000
#define DIM  64
#define NV   (NN * DIM)
#define EMAX 1250000
#define ALPHA 0.25f
#define NB_SCAN ((NN + 1023) / 1024)   // 196
#define NBIN 64

// Scratch (device globals — no allocation allowed).
// NOTE: never pass these symbols from host code; select inside kernels.
__device__ float g_x1[NV];
__device__ float g_x2[NV];
__device__ float g_out[NV];
__device__ float g_dis[NN];
__device__ int   g_deg[NN];
__device__ int   g_off[NN];
__device__ int   g_cur[NN];
__device__ int   g_bsum[NB_SCAN];
__device__ int   g_bpre[NB_SCAN];
__device__ int2  g_pack[EMAX];   // (src, wgt-bits) packed: one LDG.64 per edge
__device__ int   g_hist[NBIN];
__device__ int   g_hoff[NBIN];
__device__ int   g_hcur[NBIN];
__device__ int   g_perm[NN];     // nodes sorted by degree

// ---- init ----
__global__ void k_deg0() {
    int i = blockIdx.x * blockDim.x + threadIdx.x;
    if (i < NN) { g_deg[i] = 0; g_cur[i] = 0; }
    if (i < NBIN) { g_hist[i] = 0; g_hcur[i] = 0; }
}

__global__ void k_count(const int* __restrict__ col, int E) {
    int i = blockIdx.x * blockDim.x + threadIdx.x;
    if (i < E) atomicAdd(&g_deg[col[i]], 1);
}

// dis + degree histogram
__global__ void k_dis() {
    int i = blockIdx.x * blockDim.x + threadIdx.x;
    if (i < NN) {
        int d = g_deg[i];
        g_dis[i] = (d > 0) ? rsqrtf((float)d) : 0.f;
        atomicAdd(&g_hist[min(d, NBIN - 1)], 1);
    }
}

// ---- exclusive scan of degrees ----
__global__ void k_scan1() {
    __shared__ int s[1024];
    int tid = threadIdx.x;
    int i = blockIdx.x * 1024 + tid;
    int v = (i < NN) ? g_deg[i] : 0;
    s[tid] = v;
    __syncthreads();
    #pragma unroll
    for (int o = 1; o < 1024; o <<= 1) {
        int t = (tid >= o) ? s[tid - o] : 0;
        __syncthreads();
        s[tid] += t;
        __syncthreads();
    }
    if (i < NN) g_off[i] = s[tid] - v;
    if (tid == 1023) g_bsum[blockIdx.x] = s[1023];
}

__global__ void k_scan2() {
    __shared__ int s[256];
    int tid = threadIdx.x;
    int v = (tid < NB_SCAN) ? g_bsum[tid] : 0;
    s[tid] = v;
    __syncthreads();
    #pragma unroll
    for (int o = 1; o < 256; o <<= 1) {
        int t = (tid >= o) ? s[tid - o] : 0;
        __syncthreads();
        s[tid] += t;
        __syncthreads();
    }
    if (tid < NB_SCAN) g_bpre[tid] = s[tid] - v;
}

__global__ void k_off_final() {
    int i = blockIdx.x * blockDim.x + threadIdx.x;
    if (i < NN) g_off[i] += g_bpre[i >> 10];
}

// ---- tiny scan of the degree histogram (1 warp's worth in 1 block) ----
__global__ void k_hscan() {
    __shared__ int s[NBIN];
    int tid = threadIdx.x;
    int v = g_hist[tid];
    s[tid] = v;
    __syncthreads();
    #pragma unroll
    for (int o = 1; o < NBIN; o <<= 1) {
        int t = (tid >= o) ? s[tid - o] : 0;
        __syncthreads();
        s[tid] += t;
        __syncthreads();
    }
    g_hoff[tid] = s[tid] - v;   // exclusive
}

// ---- degree-sorted permutation (counting sort scatter) ----
__global__ void k_perm() {
    int i = blockIdx.x * blockDim.x + threadIdx.x;
    if (i >= NN) return;
    int b = min(__ldg(g_deg + i), NBIN - 1);
    int pos = __ldg(g_hoff + b) + atomicAdd(&g_hcur[b], 1);
    g_perm[pos] = i;
}

// ---- CSR fill: packed (src, wgt) per slot ----
__global__ void k_fill(const int* __restrict__ row, const int* __restrict__ col, int E) {
    int e = blockIdx.x * blockDim.x + threadIdx.x;
    if (e >= E) return;
    int r = __ldg(row + e);
    int c = __ldg(col + e);
    int slot = __ldg(g_off + c) + atomicAdd(&g_cur[c], 1);
    float w = __ldg((const float*)g_dis + r) * __ldg((const float*)g_dis + c);
    g_pack[slot] = make_int2(r, __float_as_int(w));
}

// ---- gather SpMM: 16 lanes per node (2 equal-degree nodes per warp via perm),
// packed 8B edge loads, unroll-4 with independent accumulators. ----
// layer 0: emb -> g_x1 ; layer 1: g_x1 -> g_x2
__global__ void k_gather(const float* __restrict__ emb, int layer) {
    int t = blockIdx.x * blockDim.x + threadIdx.x;
    int slot = t >> 4;
    int j = t & 15;
    if (slot >= NN) return;
    int node = __ldg(g_perm + slot);

    const float4* x  = (layer == 0) ? (const float4*)emb  : (const float4*)g_x1;
    float4*       xn = (layer == 0) ? (float4*)g_x1 : (float4*)g_x2;

    int beg = __ldg(g_off + node);
    int deg = __ldg(g_deg + node);

    float4 A0 = make_float4(0.f, 0.f, 0.f, 0.f), A1 = A0, A2 = A0, A3 = A0;

    int k = 0;
    for (; k + 4 <= deg; k += 4) {
        int2 p0 = __ldg(g_pack + beg + k);
        int2 p1 = __ldg(g_pack + beg + k + 1);
        int2 p2 = __ldg(g_pack + beg + k + 2);
        int2 p3 = __ldg(g_pack + beg + k + 3);
        float4 v0 = __ldg(x + (size_t)p0.x * 16 + j);
        float4 v1 = __ldg(x + (size_t)p1.x * 16 + j);
        float4 v2 = __ldg(x + (size_t)p2.x * 16 + j);
        float4 v3 = __ldg(x + (size_t)p3.x * 16 + j);
        float w0 = __int_as_float(p0.y), w1 = __int_as_float(p1.y);
        float w2 = __int_as_float(p2.y), w3 = __int_as_float(p3.y);
        A0.x += w0 * v0.x; A0.y += w0 * v0.y; A0.z += w0 * v0.z; A0.w += w0 * v0.w;
        A1.x += w1 * v1.x; A1.y += w1 * v1.y; A1.z += w1 * v1.z; A1.w += w1 * v1.w;
        A2.x += w2 * v2.x; A2.y += w2 * v2.y; A2.z += w2 * v2.z; A2.w += w2 * v2.w;
        A3.x += w3 * v3.x; A3.y += w3 * v3.y; A3.z += w3 * v3.z; A3.w += w3 * v3.w;
    }
    if (k + 2 <= deg) {
        int2 p0 = __ldg(g_pack + beg + k);
        int2 p1 = __ldg(g_pack + beg + k + 1);
        float4 v0 = __ldg(x + (size_t)p0.x * 16 + j);
        float4 v1 = __ldg(x + (size_t)p1.x * 16 + j);
        float w0 = __int_as_float(p0.y), w1 = __int_as_float(p1.y);
        A0.x += w0 * v0.x; A0.y += w0 * v0.y; A0.z += w0 * v0.z; A0.w += w0 * v0.w;
        A1.x += w1 * v1.x; A1.y += w1 * v1.y; A1.z += w1 * v1.z; A1.w += w1 * v1.w;
        k += 2;
    }
    if (k < deg) {
        int2 p0 = __ldg(g_pack + beg + k);
        float4 v0 = __ldg(x + (size_t)p0.x * 16 + j);
        float w0 = __int_as_float(p0.y);
        A2.x += w0 * v0.x; A2.y += w0 * v0.y; A2.z += w0 * v0.z; A2.w += w0 * v0.w;
    }

    float4 acc;
    acc.x = (A0.x + A1.x) + (A2.x + A3.x);
    acc.y = (A0.y + A1.y) + (A2.y + A3.y);
    acc.z = (A0.z + A1.z) + (A2.z + A3.z);
    acc.w = (A0.w + A1.w) + (A2.w + A3.w);
    xn[(size_t)node * 16 + j] = acc;
}

// ---- final layer fused with alpha-combine: out = 0.25*(emb+x1+x2+gather(x2))
__global__ void k_gather_final(const float* __restrict__ emb) {
    int t = blockIdx.x * blockDim.x + threadIdx.x;
    int slot = t >> 4;
    int j = t & 15;
    if (slot >= NN) return;
    int node = __ldg(g_perm + slot);

    const float4* x = (const float4*)g_x2;
    int beg = __ldg(g_off + node);
    int deg = __ldg(g_deg + node);

    float4 A0 = make_float4(0.f, 0.f, 0.f, 0.f), A1 = A0, A2 = A0, A3 = A0;

    int k = 0;
    for (; k + 4 <= deg; k += 4) {
        int2 p0 = __ldg(g_pack + beg + k);
        int2 p1 = __ldg(g_pack + beg + k + 1);
        int2 p2 = __ldg(g_pack + beg + k + 2);
        int2 p3 = __ldg(g_pack + beg + k + 3);
        float4 v0 = __ldg(x + (size_t)p0.x * 16 + j);
        float4 v1 = __ldg(x + (size_t)p1.x * 16 + j);
        float4 v2 = __ldg(x + (size_t)p2.x * 16 + j);
        float4 v3 = __ldg(x + (size_t)p3.x * 16 + j);
        float w0 = __int_as_float(p0.y), w1 = __int_as_float(p1.y);
        float w2 = __int_as_float(p2.y), w3 = __int_as_float(p3.y);
        A0.x += w0 * v0.x; A0.y += w0 * v0.y; A0.z += w0 * v0.z; A0.w += w0 * v0.w;
        A1.x += w1 * v1.x; A1.y += w1 * v1.y; A1.z += w1 * v1.z; A1.w += w1 * v1.w;
        A2.x += w2 * v2.x; A2.y += w2 * v2.y; A2.z += w2 * v2.z; A2.w += w2 * v2.w;
        A3.x += w3 * v3.x; A3.y += w3 * v3.y; A3.z += w3 * v3.z; A3.w += w3 * v3.w;
    }
    if (k + 2 <= deg) {
        int2 p0 = __ldg(g_pack + beg + k);
        int2 p1 = __ldg(g_pack + beg + k + 1);
        float4 v0 = __ldg(x + (size_t)p0.x * 16 + j);
        float4 v1 = __ldg(x + (size_t)p1.x * 16 + j);
        float w0 = __int_as_float(p0.y), w1 = __int_as_float(p1.y);
        A0.x += w0 * v0.x; A0.y += w0 * v0.y; A0.z += w0 * v0.z; A0.w += w0 * v0.w;
        A1.x += w1 * v1.x; A1.y += w1 * v1.y; A1.z += w1 * v1.z; A1.w += w1 * v1.w;
        k += 2;
    }
    if (k < deg) {
        int2 p0 = __ldg(g_pack + beg + k);
        float4 v0 = __ldg(x + (size_t)p0.x * 16 + j);
        float w0 = __int_as_float(p0.y);
        A2.x += w0 * v0.x; A2.y += w0 * v0.y; A2.z += w0 * v0.z; A2.w += w0 * v0.w;
    }

    size_t idx = (size_t)node * 16 + j;
    float4 a = __ldg((const float4*)emb + idx);
    float4 b = ((const float4*)g_x1)[idx];
    float4 c = ((const float4*)g_x2)[idx];
    float4 o;
    o.x = ALPHA * (a.x + b.x + c.x + ((A0.x + A1.x) + (A2.x + A3.x)));
    o.y = ALPHA * (a.y + b.y + c.y + ((A0.y + A1.y) + (A2.y + A3.y)));
    o.z = ALPHA * (a.z + b.z + c.z + ((A0.z + A1.z) + (A2.z + A3.z)));
    o.w = ALPHA * (a.w + b.w + c.w + ((A0.w + A1.w) + (A2.w + A3.w)));
    ((float4*)g_out)[idx] = o;
}

// ---- scoring: 16 lanes per (user,item) pair, float4 loads ----
__global__ void k_score(const int* __restrict__ batch, float* __restrict__ out, int P) {
    int t = blockIdx.x * blockDim.x + threadIdx.x;
    int p = t >> 4;
    int lane = t & 15;
    if (p >= P) return;
    int u = __ldg(batch + 3 * p);
    int v = __ldg(batch + 3 * p + 1);
    float4 a = __ldg((const float4*)g_out + (size_t)u * 16 + lane);
    float4 b = __ldg((const float4*)g_out + (size_t)v * 16 + lane);
    float s = a.x * b.x + a.y * b.y + a.z * b.z + a.w * b.w;
    #pragma unroll
    for (int o = 8; o; o >>= 1) s += __shfl_xor_sync(0xFFFFFFFFu, s, o);
    if (lane == 0) out[p] = s;
}

extern "C" void kernel_launch(void* const* d_in, const int* in_sizes, int n_in,
                              void* d_out, int out_size) {
    const float* emb   = (const float*)d_in[0];
    const int*   ei    = (const int*)d_in[1];
    const int*   batch = (const int*)d_in[2];
    float*       out   = (float*)d_out;

    int E = in_sizes[1] / 2;
    const int* row = ei;
    const int* col = ei + E;
    int P = in_sizes[2] / 3;

    k_deg0<<<(NN + 255) / 256, 256>>>();
    k_count<<<(E + 255) / 256, 256>>>(col, E);
    k_dis<<<(NN + 255) / 256, 256>>>();
    k_scan1<<<NB_SCAN, 1024>>>();
    k_scan2<<<1, 256>>>();
    k_off_final<<<(NN + 255) / 256, 256>>>();
    k_hscan<<<1, NBIN>>>();
    k_perm<<<(NN + 255) / 256, 256>>>();
    k_fill<<<(E + 255) / 256, 256>>>(row, col, E);

    int gthreads = NN * 16;
    int gblocks = (gthreads + 255) / 256;
    k_gather<<<gblocks, 256>>>(emb, 0);
    k_gather<<<gblocks, 256>>>(emb, 1);
    k_gather_final<<<gblocks, 256>>>(emb);

    long long sthreads = (long long)P * 16;
    k_score<<<(int)((sthreads + 255) / 256), 256>>>(batch, out, P);
}

// round 7
// speedup vs baseline: 1.2478x; 1.2478x over previous
#include <cuda_runtime.h>

#define NN   200000
#define DIM  64
#define NV   (NN * DIM)
#define EMAX 1250000
#define ALPHA 0.25f
#define NB_SCAN ((NN + 1023) / 1024)   // 196

// Scratch (device globals — no allocation allowed).
// NOTE: never pass these symbols from host code; select inside kernels.
__device__ float g_x1[NV];
__device__ float g_x2[NV];
__device__ float g_out[NV];
__device__ float g_dis[NN];
__device__ int   g_deg[NN];
__device__ int   g_off[NN];      // block-local exclusive prefix (add g_bpre[i>>10])
__device__ int   g_cur[NN];
__device__ int   g_bsum[NB_SCAN];
__device__ int   g_bpre[NB_SCAN];
__device__ int2  g_pack[EMAX];   // (src, wgt-bits): one LDG.64 per edge

// ---- init ----
__global__ void k_deg0() {
    int i = blockIdx.x * blockDim.x + threadIdx.x;
    if (i < NN) { g_deg[i] = 0; g_cur[i] = 0; }
}

__global__ void k_count(const int* __restrict__ col, int E) {
    int i = blockIdx.x * blockDim.x + threadIdx.x;
    if (i < E) atomicAdd(&g_deg[col[i]], 1);
}

// ---- scan of degrees, fused with dis = deg^{-1/2} ----
__global__ void k_scan1() {
    __shared__ int s[1024];
    int tid = threadIdx.x;
    int i = blockIdx.x * 1024 + tid;
    int v = (i < NN) ? g_deg[i] : 0;
    if (i < NN) g_dis[i] = (v > 0) ? rsqrtf((float)v) : 0.f;
    s[tid] = v;
    __syncthreads();
    #pragma unroll
    for (int o = 1; o < 1024; o <<= 1) {
        int t = (tid >= o) ? s[tid - o] : 0;
        __syncthreads();
        s[tid] += t;
        __syncthreads();
    }
    if (i < NN) g_off[i] = s[tid] - v;   // block-local exclusive
    if (tid == 1023) g_bsum[blockIdx.x] = s[1023];
}

__global__ void k_scan2() {
    __shared__ int s[256];
    int tid = threadIdx.x;
    int v = (tid < NB_SCAN) ? g_bsum[tid] : 0;
    s[tid] = v;
    __syncthreads();
    #pragma unroll
    for (int o = 1; o < 256; o <<= 1) {
        int t = (tid >= o) ? s[tid - o] : 0;
        __syncthreads();
        s[tid] += t;
        __syncthreads();
    }
    if (tid < NB_SCAN) g_bpre[tid] = s[tid] - v;
}

// ---- CSR fill: packed (src, wgt) per slot; block-prefix folded in ----
__global__ void k_fill(const int* __restrict__ row, const int* __restrict__ col, int E) {
    int e = blockIdx.x * blockDim.x + threadIdx.x;
    if (e >= E) return;
    int r = __ldg(row + e);
    int c = __ldg(col + e);
    int base = __ldg(g_off + c) + __ldg(g_bpre + (c >> 10));
    int slot = base + atomicAdd(&g_cur[c], 1);
    float w = __ldg((const float*)g_dis + r) * __ldg((const float*)g_dis + c);
    g_pack[slot] = make_int2(r, __float_as_int(w));
}

// ---- gather SpMM: 16 lanes per node (natural order), packed 8B edge loads,
// unroll-4 with 4 independent accumulators. ----
// layer 0: emb -> g_x1 ; layer 1: g_x1 -> g_x2
__global__ void k_gather(const float* __restrict__ emb, int layer) {
    int t = blockIdx.x * blockDim.x + threadIdx.x;
    int node = t >> 4;
    int j = t & 15;
    if (node >= NN) return;

    const float4* x  = (layer == 0) ? (const float4*)emb  : (const float4*)g_x1;
    float4*       xn = (layer == 0) ? (float4*)g_x1 : (float4*)g_x2;

    int beg = __ldg(g_off + node) + __ldg(g_bpre + (node >> 10));
    int deg = __ldg(g_deg + node);

    float4 A0 = make_float4(0.f, 0.f, 0.f, 0.f), A1 = A0, A2 = A0, A3 = A0;

    int k = 0;
    for (; k + 4 <= deg; k += 4) {
        int2 p0 = __ldg(g_pack + beg + k);
        int2 p1 = __ldg(g_pack + beg + k + 1);
        int2 p2 = __ldg(g_pack + beg + k + 2);
        int2 p3 = __ldg(g_pack + beg + k + 3);
        float4 v0 = __ldg(x + (size_t)p0.x * 16 + j);
        float4 v1 = __ldg(x + (size_t)p1.x * 16 + j);
        float4 v2 = __ldg(x + (size_t)p2.x * 16 + j);
        float4 v3 = __ldg(x + (size_t)p3.x * 16 + j);
        float w0 = __int_as_float(p0.y), w1 = __int_as_float(p1.y);
        float w2 = __int_as_float(p2.y), w3 = __int_as_float(p3.y);
        A0.x += w0 * v0.x; A0.y += w0 * v0.y; A0.z += w0 * v0.z; A0.w += w0 * v0.w;
        A1.x += w1 * v1.x; A1.y += w1 * v1.y; A1.z += w1 * v1.z; A1.w += w1 * v1.w;
        A2.x += w2 * v2.x; A2.y += w2 * v2.y; A2.z += w2 * v2.z; A2.w += w2 * v2.w;
        A3.x += w3 * v3.x; A3.y += w3 * v3.y; A3.z += w3 * v3.z; A3.w += w3 * v3.w;
    }
    if (k + 2 <= deg) {
        int2 p0 = __ldg(g_pack + beg + k);
        int2 p1 = __ldg(g_pack + beg + k + 1);
        float4 v0 = __ldg(x + (size_t)p0.x * 16 + j);
        float4 v1 = __ldg(x + (size_t)p1.x * 16 + j);
        float w0 = __int_as_float(p0.y), w1 = __int_as_float(p1.y);
        A0.x += w0 * v0.x; A0.y += w0 * v0.y; A0.z += w0 * v0.z; A0.w += w0 * v0.w;
        A1.x += w1 * v1.x; A1.y += w1 * v1.y; A1.z += w1 * v1.z; A1.w += w1 * v1.w;
        k += 2;
    }
    if (k < deg) {
        int2 p0 = __ldg(g_pack + beg + k);
        float4 v0 = __ldg(x + (size_t)p0.x * 16 + j);
        float w0 = __int_as_float(p0.y);
        A2.x += w0 * v0.x; A2.y += w0 * v0.y; A2.z += w0 * v0.z; A2.w += w0 * v0.w;
    }

    float4 acc;
    acc.x = (A0.x + A1.x) + (A2.x + A3.x);
    acc.y = (A0.y + A1.y) + (A2.y + A3.y);
    acc.z = (A0.z + A1.z) + (A2.z + A3.z);
    acc.w = (A0.w + A1.w) + (A2.w + A3.w);
    xn[(size_t)node * 16 + j] = acc;
}

// ---- final layer fused with alpha-combine: out = 0.25*(emb+x1+x2+gather(x2))
__global__ void k_gather_final(const float* __restrict__ emb) {
    int t = blockIdx.x * blockDim.x + threadIdx.x;
    int node = t >> 4;
    int j = t & 15;
    if (node >= NN) return;

    const float4* x = (const float4*)g_x2;
    int beg = __ldg(g_off + node) + __ldg(g_bpre + (node >> 10));
    int deg = __ldg(g_deg + node);

    float4 A0 = make_float4(0.f, 0.f, 0.f, 0.f), A1 = A0, A2 = A0, A3 = A0;

    int k = 0;
    for (; k + 4 <= deg; k += 4) {
        int2 p0 = __ldg(g_pack + beg + k);
        int2 p1 = __ldg(g_pack + beg + k + 1);
        int2 p2 = __ldg(g_pack + beg + k + 2);
        int2 p3 = __ldg(g_pack + beg + k + 3);
        float4 v0 = __ldg(x + (size_t)p0.x * 16 + j);
        float4 v1 = __ldg(x + (size_t)p1.x * 16 + j);
        float4 v2 = __ldg(x + (size_t)p2.x * 16 + j);
        float4 v3 = __ldg(x + (size_t)p3.x * 16 + j);
        float w0 = __int_as_float(p0.y), w1 = __int_as_float(p1.y);
        float w2 = __int_as_float(p2.y), w3 = __int_as_float(p3.y);
        A0.x += w0 * v0.x; A0.y += w0 * v0.y; A0.z += w0 * v0.z; A0.w += w0 * v0.w;
        A1.x += w1 * v1.x; A1.y += w1 * v1.y; A1.z += w1 * v1.z; A1.w += w1 * v1.w;
        A2.x += w2 * v2.x; A2.y += w2 * v2.y; A2.z += w2 * v2.z; A2.w += w2 * v2.w;
        A3.x += w3 * v3.x; A3.y += w3 * v3.y; A3.z += w3 * v3.z; A3.w += w3 * v3.w;
    }
    if (k + 2 <= deg) {
        int2 p0 = __ldg(g_pack + beg + k);
        int2 p1 = __ldg(g_pack + beg + k + 1);
        float4 v0 = __ldg(x + (size_t)p0.x * 16 + j);
        float4 v1 = __ldg(x + (size_t)p1.x * 16 + j);
        float w0 = __int_as_float(p0.y), w1 = __int_as_float(p1.y);
        A0.x += w0 * v0.x; A0.y += w0 * v0.y; A0.z += w0 * v0.z; A0.w += w0 * v0.w;
        A1.x += w1 * v1.x; A1.y += w1 * v1.y; A1.z += w1 * v1.z; A1.w += w1 * v1.w;
        k += 2;
    }
    if (k < deg) {
        int2 p0 = __ldg(g_pack + beg + k);
        float4 v0 = __ldg(x + (size_t)p0.x * 16 + j);
        float w0 = __int_as_float(p0.y);
        A2.x += w0 * v0.x; A2.y += w0 * v0.y; A2.z += w0 * v0.z; A2.w += w0 * v0.w;
    }

    size_t idx = (size_t)node * 16 + j;
    float4 a = __ldg((const float4*)emb + idx);
    float4 b = ((const float4*)g_x1)[idx];
    float4 c = ((const float4*)g_x2)[idx];
    float4 o;
    o.x = ALPHA * (a.x + b.x + c.x + ((A0.x + A1.x) + (A2.x + A3.x)));
    o.y = ALPHA * (a.y + b.y + c.y + ((A0.y + A1.y) + (A2.y + A3.y)));
    o.z = ALPHA * (a.z + b.z + c.z + ((A0.z + A1.z) + (A2.z + A3.z)));
    o.w = ALPHA * (a.w + b.w + c.w + ((A0.w + A1.w) + (A2.w + A3.w)));
    ((float4*)g_out)[idx] = o;
}

// ---- scoring: 16 lanes per (user,item) pair, float4 loads ----
__global__ void k_score(const int* __restrict__ batch, float* __restrict__ out, int P) {
    int t = blockIdx.x * blockDim.x + threadIdx.x;
    int p = t >> 4;
    int lane = t & 15;
    if (p >= P) return;
    int u = __ldg(batch + 3 * p);
    int v = __ldg(batch + 3 * p + 1);
    float4 a = __ldg((const float4*)g_out + (size_t)u * 16 + lane);
    float4 b = __ldg((const float4*)g_out + (size_t)v * 16 + lane);
    float s = a.x * b.x + a.y * b.y + a.z * b.z + a.w * b.w;
    #pragma unroll
    for (int o = 8; o; o >>= 1) s += __shfl_xor_sync(0xFFFFFFFFu, s, o);
    if (lane == 0) out[p] = s;
}

extern "C" void kernel_launch(void* const* d_in, const int* in_sizes, int n_in,
                              void* d_out, int out_size) {
    const float* emb   = (const float*)d_in[0];
    const int*   ei    = (const int*)d_in[1];
    const int*   batch = (const int*)d_in[2];
    float*       out   = (float*)d_out;

    int E = in_sizes[1] / 2;
    const int* row = ei;
    const int* col = ei + E;
    int P = in_sizes[2] / 3;

    // launch indices:        0       1        2        3        4       5..7       8
    k_deg0<<<(NN + 255) / 256, 256>>>();
    k_count<<<(E + 255) / 256, 256>>>(col, E);
    k_scan1<<<NB_SCAN, 1024>>>();
    k_scan2<<<1, 256>>>();
    k_fill<<<(E + 255) / 256, 256>>>(row, col, E);

    int gthreads = NN * 16;
    int gblocks = (gthreads + 255) / 256;
    k_gather<<<gblocks, 256>>>(emb, 0);     // <- ncu -s 5 should land here
    k_gather<<<gblocks, 256>>>(emb, 1);
    k_gather_final<<<gblocks, 256>>>(emb);

    long long sthreads = (long long)P * 16;
    k_score<<<(int)((sthreads + 255) / 256), 256>>>(batch, out, P);
}